// round 14
// baseline (speedup 1.0000x reference)
#include <cuda_runtime.h>
#include <cstddef>

#define NR 8192
#define SB 64                                  // stat bins per quantity
static const long long NN = (long long)NR * NR;

// ---------------- device scratch (no allocations allowed) ----------------
// layout: row (2*slot)   = partial sums   (SB bins)
//         row (2*slot+1) = partial sumsqs (SB bins)
// slots: 0=blk1, 1=blk3, 2=blk2, 3=blk4, 4=blkC1, 5=blkC2
__device__ double g_stats[12 * SB];            // zero at module load
__device__ __align__(16) float g_r1[NR * 4];   // mv4 outputs, TRANSPOSED [4][NR]
__device__ __align__(16) float g_r2[NR * 4];
__device__ __align__(16) float g_z1[NR];       // mv1 outputs [NR]
__device__ __align__(16) float g_z2[NR];

// ---------------- BN param finalize: one warp, result -> smem[2] ----------
__device__ __forceinline__ void bn_warp(int slot, float Mcount,
                                        float gamma, float beta,
                                        volatile float* out2) {
    int lane = threadIdx.x & 31;
    double s = g_stats[(2 * slot) * SB + lane] +
               g_stats[(2 * slot) * SB + lane + 32];
    double q = g_stats[(2 * slot + 1) * SB + lane] +
               g_stats[(2 * slot + 1) * SB + lane + 32];
#pragma unroll
    for (int off = 16; off; off >>= 1) {
        s += __shfl_xor_sync(0xffffffffu, s, off);
        q += __shfl_xor_sync(0xffffffffu, q, off);
    }
    if (lane == 0) {
        double mean = s / (double)Mcount;
        double var  = q / (double)Mcount - mean * mean;
        float sc = gamma * rsqrtf((float)var + 1e-5f);
        out2[0] = sc;
        out2[1] = beta - sc * (float)mean;     // y = sc*x + sh
    }
}

// ---------------- epilogues ------------------------------------------------
__device__ __forceinline__ void mv4_epilogue(const float (&acc)[8][4],
                                             float* __restrict__ rT,
                                             const float* __restrict__ b,
                                             int slot, int row0, int bin) {
    __shared__ float sred[8][32];
    int tid = threadIdx.x, lane = tid & 31, warp = tid >> 5;
#pragma unroll
    for (int v = 0; v < 32; v++) {
        float val = acc[v >> 2][v & 3];
#pragma unroll
        for (int off = 16; off; off >>= 1)
            val += __shfl_xor_sync(0xffffffffu, val, off);
        if (lane == v) sred[warp][v] = val;
    }
    __syncthreads();
    if (warp == 0) {
        float h = 0.f;
#pragma unroll
        for (int w = 0; w < 8; w++) h += sred[w][lane];
        h += b[lane & 3];
        float rv = fmaxf(h, 0.f);
        // transposed store: rT[j][row]
        rT[(lane & 3) * NR + row0 + (lane >> 2)] = rv;
        float s = rv, q = rv * rv;
#pragma unroll
        for (int off = 16; off; off >>= 1) {
            s += __shfl_xor_sync(0xffffffffu, s, off);
            q += __shfl_xor_sync(0xffffffffu, q, off);
        }
        if (lane == 0) {
            atomicAdd(&g_stats[(2 * slot) * SB + bin], (double)s);
            atomicAdd(&g_stats[(2 * slot + 1) * SB + bin], (double)q);
        }
    }
}

__device__ __forceinline__ void mv1_epilogue(const float (&acc)[8],
                                             float* __restrict__ outv,
                                             const float* __restrict__ b,
                                             int slot, int row0, int bin) {
    __shared__ float sred[8][8];
    int tid = threadIdx.x, lane = tid & 31, warp = tid >> 5;
#pragma unroll
    for (int v = 0; v < 8; v++) {
        float val = acc[v];
#pragma unroll
        for (int off = 16; off; off >>= 1)
            val += __shfl_xor_sync(0xffffffffu, val, off);
        if (lane == v) sred[warp][v] = val;
    }
    __syncthreads();
    if (warp == 0) {
        float rv = 0.f;
        if (lane < 8) {
            float h = 0.f;
#pragma unroll
            for (int w = 0; w < 8; w++) h += sred[w][lane];
            h += b[0];
            rv = fmaxf(h, 0.f);
            outv[row0 + lane] = rv;
        }
        float s = rv, q = rv * rv;
#pragma unroll
        for (int off = 16; off; off >>= 1) {
            s += __shfl_xor_sync(0xffffffffu, s, off);
            q += __shfl_xor_sync(0xffffffffu, q, off);
        }
        if (lane == 0) {
            atomicAdd(&g_stats[(2 * slot) * SB + bin], (double)s);
            atomicAdd(&g_stats[(2 * slot + 1) * SB + bin], (double)q);
        }
    }
}

// ============ stage 1: blocks 1 & 3 (dual), z = x * w on the fly ==========
__global__ void __launch_bounds__(256) k_mv4_s1(
    const float* __restrict__ A1, const float* __restrict__ A2,
    const float* __restrict__ x,
    const float* __restrict__ w11, const float* __restrict__ b11,
    const float* __restrict__ w21, const float* __restrict__ b21, int bpm) {
    int mat = blockIdx.x >= bpm;
    const float4* __restrict__ A4 = (const float4*)(mat ? A2 : A1);
    const float*  w  = mat ? w21 : w11;
    const float*  b  = mat ? b21 : b11;
    const float4* x4 = (const float4*)(x + mat * NR);
    float* rT = mat ? g_r2 : g_r1;
    int row0 = (blockIdx.x - mat * bpm) * 8;
    int tid = threadIdx.x;

    float w0 = w[0], w1 = w[1], w2 = w[2], w3 = w[3];

    float acc[8][4];
#pragma unroll
    for (int r = 0; r < 8; r++)
#pragma unroll
        for (int j = 0; j < 4; j++) acc[r][j] = 0.f;

#pragma unroll 2
    for (int it = 0; it < 8; it++) {
        int cg = it * 256 + tid;
        float4 xv = x4[cg];
        float4 za = {xv.x * w0, xv.x * w1, xv.x * w2, xv.x * w3};
        float4 zb = {xv.y * w0, xv.y * w1, xv.y * w2, xv.y * w3};
        float4 zc = {xv.z * w0, xv.z * w1, xv.z * w2, xv.z * w3};
        float4 zd = {xv.w * w0, xv.w * w1, xv.w * w2, xv.w * w3};
#pragma unroll
        for (int r = 0; r < 8; r++) {
            float4 av = A4[(size_t)(row0 + r) * 2048 + cg];
            acc[r][0] += av.x * za.x + av.y * zb.x + av.z * zc.x + av.w * zd.x;
            acc[r][1] += av.x * za.y + av.y * zb.y + av.z * zc.y + av.w * zd.y;
            acc[r][2] += av.x * za.z + av.y * zb.z + av.z * zc.z + av.w * zd.z;
            acc[r][3] += av.x * za.w + av.y * zb.w + av.z * zc.w + av.w * zd.w;
        }
    }
    mv4_epilogue(acc, rT, b, mat, row0, blockIdx.x & (SB - 1));
}

// ====== stage 2: blocks 2 & 4 (dual), z = BN(r)·w folded on the fly =======
__global__ void __launch_bounds__(256) k_mv1_s2(
    const float* __restrict__ A1, const float* __restrict__ A2,
    const float* __restrict__ w12, const float* __restrict__ b12,
    const float* __restrict__ w22, const float* __restrict__ b22,
    const float* __restrict__ gamma, const float* __restrict__ beta, int bpm) {
    int mat = blockIdx.x >= bpm;
    const float4* __restrict__ A4  = (const float4*)(mat ? A2 : A1);
    const float*  w = mat ? w22 : w12;
    const float*  b = mat ? b22 : b12;
    const float4* __restrict__ rT4 = (const float4*)(mat ? g_r2 : g_r1);
    float* outv = mat ? g_z2 : g_z1;
    int row0 = (blockIdx.x - mat * bpm) * 8;
    int tid = threadIdx.x;

    __shared__ float sbn[2];
    if (tid < 32) bn_warp(mat, 4.f * NR, *gamma, *beta, sbn);
    __syncthreads();
    float sc = sbn[0];
    float c0 = sc * w[0], c1 = sc * w[1], c2 = sc * w[2], c3 = sc * w[3];
    float shw = sbn[1] * (w[0] + w[1] + w[2] + w[3]);

    float acc[8];
#pragma unroll
    for (int r = 0; r < 8; r++) acc[r] = 0.f;

#pragma unroll 2
    for (int it = 0; it < 8; it++) {
        int cg = it * 256 + tid;
        float4 r0 = rT4[cg];
        float4 r1 = rT4[2048 + cg];
        float4 r2 = rT4[4096 + cg];
        float4 r3 = rT4[6144 + cg];
        float4 zv;
        zv.x = r0.x * c0 + r1.x * c1 + r2.x * c2 + r3.x * c3 + shw;
        zv.y = r0.y * c0 + r1.y * c1 + r2.y * c2 + r3.y * c3 + shw;
        zv.z = r0.z * c0 + r1.z * c1 + r2.z * c2 + r3.z * c3 + shw;
        zv.w = r0.w * c0 + r1.w * c1 + r2.w * c2 + r3.w * c3 + shw;
#pragma unroll
        for (int r = 0; r < 8; r++) {
            float4 av = A4[(size_t)(row0 + r) * 2048 + cg];
            acc[r] += av.x * zv.x + av.y * zv.y + av.z * zv.z + av.w * zv.w;
        }
    }
    mv1_epilogue(acc, outv, b, 2 + mat, row0, blockIdx.x & (SB - 1));
}

// ====== stage 3: block C1, z[c][j] = relu(BN(f1))·wc1a + relu(BN(f2))·wc1b =
__global__ void __launch_bounds__(256) k_mv4_c1(
    const float* __restrict__ A12, const float* __restrict__ wc1,
    const float* __restrict__ bc1,
    const float* __restrict__ gamma, const float* __restrict__ beta) {
    int tid = threadIdx.x;
    // re-zero stats for next call: slots 0,1 ([0,256)) and slot 5 ([640,768))
    if (blockIdx.x == 0) {
        if (tid < 256) g_stats[tid] = 0.0;
        int t2 = tid - 256;
        if (t2 >= 0 && t2 < 128) g_stats[640 + t2] = 0.0;
    }
    __shared__ float sbn[4];                    // sc2, sh2, sc3, sh3
    if (tid < 32)      bn_warp(2, (float)NR, *gamma, *beta, sbn);
    else if (tid < 64) bn_warp(3, (float)NR, *gamma, *beta, sbn + 2);
    __syncthreads();
    float sc2 = sbn[0], sh2 = sbn[1], sc3 = sbn[2], sh3 = sbn[3];
    float wa0 = wc1[0], wa1 = wc1[1], wa2 = wc1[2], wa3 = wc1[3];
    float wb0 = wc1[4], wb1 = wc1[5], wb2 = wc1[6], wb3 = wc1[7];

    const float4* __restrict__ A4   = (const float4*)A12;
    const float4* __restrict__ z1_4 = (const float4*)g_z1;
    const float4* __restrict__ z2_4 = (const float4*)g_z2;
    int row0 = blockIdx.x * 8;

    float acc[8][4];
#pragma unroll
    for (int r = 0; r < 8; r++)
#pragma unroll
        for (int j = 0; j < 4; j++) acc[r][j] = 0.f;

#pragma unroll 2
    for (int it = 0; it < 8; it++) {
        int cg = it * 256 + tid;
        float4 u = z1_4[cg], v = z2_4[cg];
        float f1x = fmaxf(sc2 * u.x + sh2, 0.f), f2x = fmaxf(sc3 * v.x + sh3, 0.f);
        float f1y = fmaxf(sc2 * u.y + sh2, 0.f), f2y = fmaxf(sc3 * v.y + sh3, 0.f);
        float f1z = fmaxf(sc2 * u.z + sh2, 0.f), f2z = fmaxf(sc3 * v.z + sh3, 0.f);
        float f1w = fmaxf(sc2 * u.w + sh2, 0.f), f2w = fmaxf(sc3 * v.w + sh3, 0.f);
        float4 za = {f1x*wa0 + f2x*wb0, f1x*wa1 + f2x*wb1, f1x*wa2 + f2x*wb2, f1x*wa3 + f2x*wb3};
        float4 zb = {f1y*wa0 + f2y*wb0, f1y*wa1 + f2y*wb1, f1y*wa2 + f2y*wb2, f1y*wa3 + f2y*wb3};
        float4 zc = {f1z*wa0 + f2z*wb0, f1z*wa1 + f2z*wb1, f1z*wa2 + f2z*wb2, f1z*wa3 + f2z*wb3};
        float4 zd = {f1w*wa0 + f2w*wb0, f1w*wa1 + f2w*wb1, f1w*wa2 + f2w*wb2, f1w*wa3 + f2w*wb3};
#pragma unroll
        for (int r = 0; r < 8; r++) {
            float4 av = A4[(size_t)(row0 + r) * 2048 + cg];
            acc[r][0] += av.x * za.x + av.y * zb.x + av.z * zc.x + av.w * zd.x;
            acc[r][1] += av.x * za.y + av.y * zb.y + av.z * zc.y + av.w * zd.y;
            acc[r][2] += av.x * za.z + av.y * zb.z + av.z * zc.z + av.w * zd.z;
            acc[r][3] += av.x * za.w + av.y * zb.w + av.z * zc.w + av.w * zd.w;
        }
    }
    mv4_epilogue(acc, g_r1, bc1, 4, row0, blockIdx.x & (SB - 1));
}

// ====== stage 4: block C2, z = BN(r)·wc2 folded on the fly ================
__global__ void __launch_bounds__(256) k_mv1_c2(
    const float* __restrict__ A12, const float* __restrict__ wc2,
    const float* __restrict__ bc2,
    const float* __restrict__ gamma, const float* __restrict__ beta) {
    int tid = threadIdx.x;
    // re-zero stats for next call: slots 2,3 ([256,512))
    if (blockIdx.x == 0 && tid < 256) g_stats[256 + tid] = 0.0;
    __shared__ float sbn[2];
    if (tid < 32) bn_warp(4, 4.f * NR, *gamma, *beta, sbn);
    __syncthreads();
    float sc = sbn[0];
    float c0 = sc * wc2[0], c1 = sc * wc2[1], c2 = sc * wc2[2], c3 = sc * wc2[3];
    float shw = sbn[1] * (wc2[0] + wc2[1] + wc2[2] + wc2[3]);

    const float4* __restrict__ A4  = (const float4*)A12;
    const float4* __restrict__ rT4 = (const float4*)g_r1;
    int row0 = blockIdx.x * 8;

    float acc[8];
#pragma unroll
    for (int r = 0; r < 8; r++) acc[r] = 0.f;

#pragma unroll 2
    for (int it = 0; it < 8; it++) {
        int cg = it * 256 + tid;
        float4 r0 = rT4[cg];
        float4 r1 = rT4[2048 + cg];
        float4 r2 = rT4[4096 + cg];
        float4 r3 = rT4[6144 + cg];
        float4 zv;
        zv.x = r0.x * c0 + r1.x * c1 + r2.x * c2 + r3.x * c3 + shw;
        zv.y = r0.y * c0 + r1.y * c1 + r2.y * c2 + r3.y * c3 + shw;
        zv.z = r0.z * c0 + r1.z * c1 + r2.z * c2 + r3.z * c3 + shw;
        zv.w = r0.w * c0 + r1.w * c1 + r2.w * c2 + r3.w * c3 + shw;
#pragma unroll
        for (int r = 0; r < 8; r++) {
            float4 av = A4[(size_t)(row0 + r) * 2048 + cg];
            acc[r] += av.x * zv.x + av.y * zv.y + av.z * zv.z + av.w * zv.w;
        }
    }
    mv1_epilogue(acc, g_z2, bc2, 5, row0, blockIdx.x & (SB - 1));
}

// ====== stage 5: final BN + relu -> out ====================================
__global__ void k_out(const float* __restrict__ gamma,
                      const float* __restrict__ beta,
                      float* __restrict__ out) {
    int tid = threadIdx.x;
    __shared__ float sbn[2];
    if (tid < 32) bn_warp(5, (float)NR, *gamma, *beta, sbn);
    __syncthreads();
    // re-zero stats for next call: slot 4 ([512,640))
    if (blockIdx.x == 0 && tid < 128) g_stats[512 + tid] = 0.0;
    int i = blockIdx.x * 256 + tid;
    if (i < NR) out[i] = fmaxf(sbn[0] * g_z2[i] + sbn[1], 0.f);
}

// ---------------- host ----------------------------------------------------
extern "C" void kernel_launch(void* const* d_in, const int* in_sizes, int n_in,
                              void* d_out, int out_size) {
    const float* x     = (const float*)d_in[0];
    const float* adj   = (const float*)d_in[1];
    const float* w11   = (const float*)d_in[2];
    const float* b11   = (const float*)d_in[3];
    const float* w12   = (const float*)d_in[4];
    const float* b12   = (const float*)d_in[5];
    const float* w21   = (const float*)d_in[6];
    const float* b21   = (const float*)d_in[7];
    const float* w22   = (const float*)d_in[8];
    const float* b22   = (const float*)d_in[9];
    const float* wc1   = (const float*)d_in[10];
    const float* bc1   = (const float*)d_in[11];
    const float* wc2   = (const float*)d_in[12];
    const float* bc2   = (const float*)d_in[13];
    const float* gamma = (const float*)d_in[14];
    const float* beta  = (const float*)d_in[15];

    const float* A1  = adj;
    const float* A2  = adj + NN;
    const float* A12 = adj + 2 * NN;
    float* out = (float*)d_out;

    const int bpm = NR / 8;  // 1024 blocks per matrix

    k_mv4_s1<<<2 * bpm, 256>>>(A1, A2, x, w11, b11, w21, b21, bpm);
    k_mv1_s2<<<2 * bpm, 256>>>(A1, A2, w12, b12, w22, b22, gamma, beta, bpm);
    k_mv4_c1<<<bpm, 256>>>(A12, wc1, bc1, gamma, beta);
    k_mv1_c2<<<bpm, 256>>>(A12, wc2, bc2, gamma, beta);
    k_out<<<NR / 256, 256>>>(gamma, beta, out);
}

// round 15
// speedup vs baseline: 1.0016x; 1.0016x over previous
#include <cuda_runtime.h>
#include <cstddef>

#define NR 8192
#define SB 64                                  // stat bins per quantity
static const long long NN = (long long)NR * NR;

// ---------------- device scratch (no allocations allowed) ----------------
// layout: row (2*slot)   = partial sums   (SB bins)
//         row (2*slot+1) = partial sumsqs (SB bins)
// slots: 0=blk1, 1=blk3, 2=blk2, 3=blk4, 4=blkC1, 5=blkC2
__device__ double g_stats[12 * SB];            // zero at module load
__device__ __align__(16) float g_r1[NR * 4];   // mv4 outputs, TRANSPOSED [4][NR]
__device__ __align__(16) float g_r2[NR * 4];
__device__ __align__(16) float g_z1[NR];       // mv1 outputs [NR]
__device__ __align__(16) float g_z2[NR];

// ---------------- BN param finalize: one warp, result -> smem[2] ----------
__device__ __forceinline__ void bn_warp(int slot, float Mcount,
                                        float gamma, float beta,
                                        volatile float* out2) {
    int lane = threadIdx.x & 31;
    double s = g_stats[(2 * slot) * SB + lane] +
               g_stats[(2 * slot) * SB + lane + 32];
    double q = g_stats[(2 * slot + 1) * SB + lane] +
               g_stats[(2 * slot + 1) * SB + lane + 32];
#pragma unroll
    for (int off = 16; off; off >>= 1) {
        s += __shfl_xor_sync(0xffffffffu, s, off);
        q += __shfl_xor_sync(0xffffffffu, q, off);
    }
    if (lane == 0) {
        double mean = s / (double)Mcount;
        double var  = q / (double)Mcount - mean * mean;
        float sc = gamma * rsqrtf((float)var + 1e-5f);
        out2[0] = sc;
        out2[1] = beta - sc * (float)mean;     // y = sc*x + sh
    }
}

// ---------------- epilogues ------------------------------------------------
__device__ __forceinline__ void mv4_epilogue(const float (&acc)[8][4],
                                             float* __restrict__ rT,
                                             const float* __restrict__ b,
                                             int slot, int row0, int bin) {
    __shared__ float sred[8][32];
    int tid = threadIdx.x, lane = tid & 31, warp = tid >> 5;
#pragma unroll
    for (int v = 0; v < 32; v++) {
        float val = acc[v >> 2][v & 3];
#pragma unroll
        for (int off = 16; off; off >>= 1)
            val += __shfl_xor_sync(0xffffffffu, val, off);
        if (lane == v) sred[warp][v] = val;
    }
    __syncthreads();
    if (warp == 0) {
        float h = 0.f;
#pragma unroll
        for (int w = 0; w < 8; w++) h += sred[w][lane];
        h += b[lane & 3];
        float rv = fmaxf(h, 0.f);
        // transposed store: rT[j][row]
        rT[(lane & 3) * NR + row0 + (lane >> 2)] = rv;
        float s = rv, q = rv * rv;
#pragma unroll
        for (int off = 16; off; off >>= 1) {
            s += __shfl_xor_sync(0xffffffffu, s, off);
            q += __shfl_xor_sync(0xffffffffu, q, off);
        }
        if (lane == 0) {
            atomicAdd(&g_stats[(2 * slot) * SB + bin], (double)s);
            atomicAdd(&g_stats[(2 * slot + 1) * SB + bin], (double)q);
        }
    }
}

__device__ __forceinline__ void mv1_epilogue(const float (&acc)[8],
                                             float* __restrict__ outv,
                                             const float* __restrict__ b,
                                             int slot, int row0, int bin) {
    __shared__ float sred[8][8];
    int tid = threadIdx.x, lane = tid & 31, warp = tid >> 5;
#pragma unroll
    for (int v = 0; v < 8; v++) {
        float val = acc[v];
#pragma unroll
        for (int off = 16; off; off >>= 1)
            val += __shfl_xor_sync(0xffffffffu, val, off);
        if (lane == v) sred[warp][v] = val;
    }
    __syncthreads();
    if (warp == 0) {
        float rv = 0.f;
        if (lane < 8) {
            float h = 0.f;
#pragma unroll
            for (int w = 0; w < 8; w++) h += sred[w][lane];
            h += b[0];
            rv = fmaxf(h, 0.f);
            outv[row0 + lane] = rv;
        }
        float s = rv, q = rv * rv;
#pragma unroll
        for (int off = 16; off; off >>= 1) {
            s += __shfl_xor_sync(0xffffffffu, s, off);
            q += __shfl_xor_sync(0xffffffffu, q, off);
        }
        if (lane == 0) {
            atomicAdd(&g_stats[(2 * slot) * SB + bin], (double)s);
            atomicAdd(&g_stats[(2 * slot + 1) * SB + bin], (double)q);
        }
    }
}

// ============ stage 1: blocks 1 & 3 (dual), z = x * w on the fly ==========
__global__ void __launch_bounds__(256) k_mv4_s1(
    const float* __restrict__ A1, const float* __restrict__ A2,
    const float* __restrict__ x,
    const float* __restrict__ w11, const float* __restrict__ b11,
    const float* __restrict__ w21, const float* __restrict__ b21, int bpm) {
    int mat = blockIdx.x >= bpm;
    const float4* __restrict__ A4 = (const float4*)(mat ? A2 : A1);
    const float*  w  = mat ? w21 : w11;
    const float*  b  = mat ? b21 : b11;
    const float4* x4 = (const float4*)(x + mat * NR);
    float* rT = mat ? g_r2 : g_r1;
    int row0 = (blockIdx.x - mat * bpm) * 8;
    int tid = threadIdx.x;

    float w0 = w[0], w1 = w[1], w2 = w[2], w3 = w[3];

    float acc[8][4];
#pragma unroll
    for (int r = 0; r < 8; r++)
#pragma unroll
        for (int j = 0; j < 4; j++) acc[r][j] = 0.f;

#pragma unroll 2
    for (int it = 0; it < 8; it++) {
        int cg = it * 256 + tid;
        float4 xv = x4[cg];
        float4 za = {xv.x * w0, xv.x * w1, xv.x * w2, xv.x * w3};
        float4 zb = {xv.y * w0, xv.y * w1, xv.y * w2, xv.y * w3};
        float4 zc = {xv.z * w0, xv.z * w1, xv.z * w2, xv.z * w3};
        float4 zd = {xv.w * w0, xv.w * w1, xv.w * w2, xv.w * w3};
#pragma unroll
        for (int r = 0; r < 8; r++) {
            float4 av = A4[(size_t)(row0 + r) * 2048 + cg];
            acc[r][0] += av.x * za.x + av.y * zb.x + av.z * zc.x + av.w * zd.x;
            acc[r][1] += av.x * za.y + av.y * zb.y + av.z * zc.y + av.w * zd.y;
            acc[r][2] += av.x * za.z + av.y * zb.z + av.z * zc.z + av.w * zd.z;
            acc[r][3] += av.x * za.w + av.y * zb.w + av.z * zc.w + av.w * zd.w;
        }
    }
    mv4_epilogue(acc, rT, b, mat, row0, blockIdx.x & (SB - 1));
}

// ====== stage 2: blocks 2 & 4 (dual), z = BN(r)·w folded on the fly =======
__global__ void __launch_bounds__(256) k_mv1_s2(
    const float* __restrict__ A1, const float* __restrict__ A2,
    const float* __restrict__ w12, const float* __restrict__ b12,
    const float* __restrict__ w22, const float* __restrict__ b22,
    const float* __restrict__ gamma, const float* __restrict__ beta, int bpm) {
    int mat = blockIdx.x >= bpm;
    const float4* __restrict__ A4  = (const float4*)(mat ? A2 : A1);
    const float*  w = mat ? w22 : w12;
    const float*  b = mat ? b22 : b12;
    const float4* __restrict__ rT4 = (const float4*)(mat ? g_r2 : g_r1);
    float* outv = mat ? g_z2 : g_z1;
    int row0 = (blockIdx.x - mat * bpm) * 8;
    int tid = threadIdx.x;

    __shared__ float sbn[2];
    if (tid < 32) bn_warp(mat, 4.f * NR, *gamma, *beta, sbn);
    __syncthreads();
    float sc = sbn[0];
    float c0 = sc * w[0], c1 = sc * w[1], c2 = sc * w[2], c3 = sc * w[3];
    float shw = sbn[1] * (w[0] + w[1] + w[2] + w[3]);

    float acc[8];
#pragma unroll
    for (int r = 0; r < 8; r++) acc[r] = 0.f;

#pragma unroll 2
    for (int it = 0; it < 8; it++) {
        int cg = it * 256 + tid;
        float4 r0 = rT4[cg];
        float4 r1 = rT4[2048 + cg];
        float4 r2 = rT4[4096 + cg];
        float4 r3 = rT4[6144 + cg];
        float4 zv;
        zv.x = r0.x * c0 + r1.x * c1 + r2.x * c2 + r3.x * c3 + shw;
        zv.y = r0.y * c0 + r1.y * c1 + r2.y * c2 + r3.y * c3 + shw;
        zv.z = r0.z * c0 + r1.z * c1 + r2.z * c2 + r3.z * c3 + shw;
        zv.w = r0.w * c0 + r1.w * c1 + r2.w * c2 + r3.w * c3 + shw;
#pragma unroll
        for (int r = 0; r < 8; r++) {
            float4 av = A4[(size_t)(row0 + r) * 2048 + cg];
            acc[r] += av.x * zv.x + av.y * zv.y + av.z * zv.z + av.w * zv.w;
        }
    }
    mv1_epilogue(acc, outv, b, 2 + mat, row0, blockIdx.x & (SB - 1));
}

// ====== stage 3: block C1, z[c][j] = relu(BN(f1))·wc1a + relu(BN(f2))·wc1b =
__global__ void __launch_bounds__(256) k_mv4_c1(
    const float* __restrict__ A12, const float* __restrict__ wc1,
    const float* __restrict__ bc1,
    const float* __restrict__ gamma, const float* __restrict__ beta) {
    int tid = threadIdx.x;
    // re-zero stats for next call: slots 0,1 ([0,256)) and slot 5 ([640,768))
    if (blockIdx.x == 0) {
        if (tid < 256) g_stats[tid] = 0.0;
        int t2 = tid - 256;
        if (t2 >= 0 && t2 < 128) g_stats[640 + t2] = 0.0;
    }
    __shared__ float sbn[4];                    // sc2, sh2, sc3, sh3
    if (tid < 32)      bn_warp(2, (float)NR, *gamma, *beta, sbn);
    else if (tid < 64) bn_warp(3, (float)NR, *gamma, *beta, sbn + 2);
    __syncthreads();
    float sc2 = sbn[0], sh2 = sbn[1], sc3 = sbn[2], sh3 = sbn[3];
    float wa0 = wc1[0], wa1 = wc1[1], wa2 = wc1[2], wa3 = wc1[3];
    float wb0 = wc1[4], wb1 = wc1[5], wb2 = wc1[6], wb3 = wc1[7];

    const float4* __restrict__ A4   = (const float4*)A12;
    const float4* __restrict__ z1_4 = (const float4*)g_z1;
    const float4* __restrict__ z2_4 = (const float4*)g_z2;
    int row0 = blockIdx.x * 8;

    float acc[8][4];
#pragma unroll
    for (int r = 0; r < 8; r++)
#pragma unroll
        for (int j = 0; j < 4; j++) acc[r][j] = 0.f;

#pragma unroll 2
    for (int it = 0; it < 8; it++) {
        int cg = it * 256 + tid;
        float4 u = z1_4[cg], v = z2_4[cg];
        float f1x = fmaxf(sc2 * u.x + sh2, 0.f), f2x = fmaxf(sc3 * v.x + sh3, 0.f);
        float f1y = fmaxf(sc2 * u.y + sh2, 0.f), f2y = fmaxf(sc3 * v.y + sh3, 0.f);
        float f1z = fmaxf(sc2 * u.z + sh2, 0.f), f2z = fmaxf(sc3 * v.z + sh3, 0.f);
        float f1w = fmaxf(sc2 * u.w + sh2, 0.f), f2w = fmaxf(sc3 * v.w + sh3, 0.f);
        float4 za = {f1x*wa0 + f2x*wb0, f1x*wa1 + f2x*wb1, f1x*wa2 + f2x*wb2, f1x*wa3 + f2x*wb3};
        float4 zb = {f1y*wa0 + f2y*wb0, f1y*wa1 + f2y*wb1, f1y*wa2 + f2y*wb2, f1y*wa3 + f2y*wb3};
        float4 zc = {f1z*wa0 + f2z*wb0, f1z*wa1 + f2z*wb1, f1z*wa2 + f2z*wb2, f1z*wa3 + f2z*wb3};
        float4 zd = {f1w*wa0 + f2w*wb0, f1w*wa1 + f2w*wb1, f1w*wa2 + f2w*wb2, f1w*wa3 + f2w*wb3};
#pragma unroll
        for (int r = 0; r < 8; r++) {
            float4 av = A4[(size_t)(row0 + r) * 2048 + cg];
            acc[r][0] += av.x * za.x + av.y * zb.x + av.z * zc.x + av.w * zd.x;
            acc[r][1] += av.x * za.y + av.y * zb.y + av.z * zc.y + av.w * zd.y;
            acc[r][2] += av.x * za.z + av.y * zb.z + av.z * zc.z + av.w * zd.z;
            acc[r][3] += av.x * za.w + av.y * zb.w + av.z * zc.w + av.w * zd.w;
        }
    }
    mv4_epilogue(acc, g_r1, bc1, 4, row0, blockIdx.x & (SB - 1));
}

// ====== stage 4: block C2, z = BN(r)·wc2 folded on the fly ================
__global__ void __launch_bounds__(256) k_mv1_c2(
    const float* __restrict__ A12, const float* __restrict__ wc2,
    const float* __restrict__ bc2,
    const float* __restrict__ gamma, const float* __restrict__ beta) {
    int tid = threadIdx.x;
    // re-zero stats for next call: slots 2,3 ([256,512))
    if (blockIdx.x == 0 && tid < 256) g_stats[256 + tid] = 0.0;
    __shared__ float sbn[2];
    if (tid < 32) bn_warp(4, 4.f * NR, *gamma, *beta, sbn);
    __syncthreads();
    float sc = sbn[0];
    float c0 = sc * wc2[0], c1 = sc * wc2[1], c2 = sc * wc2[2], c3 = sc * wc2[3];
    float shw = sbn[1] * (wc2[0] + wc2[1] + wc2[2] + wc2[3]);

    const float4* __restrict__ A4  = (const float4*)A12;
    const float4* __restrict__ rT4 = (const float4*)g_r1;
    int row0 = blockIdx.x * 8;

    float acc[8];
#pragma unroll
    for (int r = 0; r < 8; r++) acc[r] = 0.f;

#pragma unroll 2
    for (int it = 0; it < 8; it++) {
        int cg = it * 256 + tid;
        float4 r0 = rT4[cg];
        float4 r1 = rT4[2048 + cg];
        float4 r2 = rT4[4096 + cg];
        float4 r3 = rT4[6144 + cg];
        float4 zv;
        zv.x = r0.x * c0 + r1.x * c1 + r2.x * c2 + r3.x * c3 + shw;
        zv.y = r0.y * c0 + r1.y * c1 + r2.y * c2 + r3.y * c3 + shw;
        zv.z = r0.z * c0 + r1.z * c1 + r2.z * c2 + r3.z * c3 + shw;
        zv.w = r0.w * c0 + r1.w * c1 + r2.w * c2 + r3.w * c3 + shw;
#pragma unroll
        for (int r = 0; r < 8; r++) {
            float4 av = A4[(size_t)(row0 + r) * 2048 + cg];
            acc[r] += av.x * zv.x + av.y * zv.y + av.z * zv.z + av.w * zv.w;
        }
    }
    mv1_epilogue(acc, g_z2, bc2, 5, row0, blockIdx.x & (SB - 1));
}

// ====== stage 5: final BN + relu -> out ====================================
__global__ void k_out(const float* __restrict__ gamma,
                      const float* __restrict__ beta,
                      float* __restrict__ out) {
    int tid = threadIdx.x;
    __shared__ float sbn[2];
    if (tid < 32) bn_warp(5, (float)NR, *gamma, *beta, sbn);
    __syncthreads();
    // re-zero stats for next call: slot 4 ([512,640))
    if (blockIdx.x == 0 && tid < 128) g_stats[512 + tid] = 0.0;
    int i = blockIdx.x * 256 + tid;
    if (i < NR) out[i] = fmaxf(sbn[0] * g_z2[i] + sbn[1], 0.f);
}

// ---------------- host ----------------------------------------------------
extern "C" void kernel_launch(void* const* d_in, const int* in_sizes, int n_in,
                              void* d_out, int out_size) {
    const float* x     = (const float*)d_in[0];
    const float* adj   = (const float*)d_in[1];
    const float* w11   = (const float*)d_in[2];
    const float* b11   = (const float*)d_in[3];
    const float* w12   = (const float*)d_in[4];
    const float* b12   = (const float*)d_in[5];
    const float* w21   = (const float*)d_in[6];
    const float* b21   = (const float*)d_in[7];
    const float* w22   = (const float*)d_in[8];
    const float* b22   = (const float*)d_in[9];
    const float* wc1   = (const float*)d_in[10];
    const float* bc1   = (const float*)d_in[11];
    const float* wc2   = (const float*)d_in[12];
    const float* bc2   = (const float*)d_in[13];
    const float* gamma = (const float*)d_in[14];
    const float* beta  = (const float*)d_in[15];

    const float* A1  = adj;
    const float* A2  = adj + NN;
    const float* A12 = adj + 2 * NN;
    float* out = (float*)d_out;

    const int bpm = NR / 8;  // 1024 blocks per matrix

    k_mv4_s1<<<2 * bpm, 256>>>(A1, A2, x, w11, b11, w21, b21, bpm);
    k_mv1_s2<<<2 * bpm, 256>>>(A1, A2, w12, b12, w22, b22, gamma, beta, bpm);
    k_mv4_c1<<<bpm, 256>>>(A12, wc1, bc1, gamma, beta);
    k_mv1_c2<<<bpm, 256>>>(A12, wc2, bc2, gamma, beta);
    k_out<<<NR / 256, 256>>>(gamma, beta, out);
}

// round 16
// speedup vs baseline: 1.3355x; 1.3334x over previous
#include <cuda_runtime.h>
#include <cstddef>

#define NR 8192
#define SB 64
static const long long NN = (long long)NR * NR;

// ---------------- device scratch (no allocations allowed) -----------------
// stats rows: (2*slot)=sums, (2*slot+1)=sumsqs; SB bins each.
// slots: 0=blk1, 1=blk3, 2=blk2, 3=blk4, 4=blkC1, 5=blkC2
__device__ double g_stats[12 * SB];               // zeroed at module load
__device__ __align__(16) float g_y1[NR], g_y2[NR];  // stage-1 raw A@x
__device__ __align__(16) float g_z1[NR], g_z2[NR];  // folded z vectors
__device__ __align__(16) float g_r1[NR], g_r2[NR];  // stage-2/C2 relu(gc)
__device__ __align__(16) float g_fa[NR], g_fb[NR];  // concat F columns
__device__ __align__(16) float g_Ga[NR], g_Gb[NR];  // C1: A12@F columns

// ---------------- BN finalize: one warp -> smem {scale, shift} ------------
__device__ __forceinline__ void bn_warp(int slot, float Mcount,
                                        float gamma, float beta,
                                        volatile float* out2) {
    int lane = threadIdx.x & 31;
    double s = g_stats[(2 * slot) * SB + lane] +
               g_stats[(2 * slot) * SB + lane + 32];
    double q = g_stats[(2 * slot + 1) * SB + lane] +
               g_stats[(2 * slot + 1) * SB + lane + 32];
#pragma unroll
    for (int off = 16; off; off >>= 1) {
        s += __shfl_xor_sync(0xffffffffu, s, off);
        q += __shfl_xor_sync(0xffffffffu, q, off);
    }
    if (lane == 0) {
        double mean = s / (double)Mcount;
        double var  = q / (double)Mcount - mean * mean;
        float sc = gamma * rsqrtf((float)var + 1e-5f);
        out2[0] = sc;
        out2[1] = beta - sc * (float)mean;   // y = sc*x + sh
    }
}

__device__ __forceinline__ void stat_add(int slot, int bin, float s, float q) {
#pragma unroll
    for (int off = 16; off; off >>= 1) {
        s += __shfl_xor_sync(0xffffffffu, s, off);
        q += __shfl_xor_sync(0xffffffffu, q, off);
    }
    if ((threadIdx.x & 31) == 0) {
        atomicAdd(&g_stats[(2 * slot) * SB + bin], (double)s);
        atomicAdd(&g_stats[(2 * slot + 1) * SB + bin], (double)q);
    }
}

// reduce 8 per-thread accumulators across block; warp0 lanes 0-7 get row sums
__device__ __forceinline__ float red8(const float (&acc)[8], float (*sred)[8]) {
    int lane = threadIdx.x & 31, warp = threadIdx.x >> 5;
#pragma unroll
    for (int v = 0; v < 8; v++) {
        float val = acc[v];
#pragma unroll
        for (int off = 16; off; off >>= 1)
            val += __shfl_xor_sync(0xffffffffu, val, off);
        if (lane == v) sred[warp][v] = val;
    }
    __syncthreads();
    float h = 0.f;
    if (warp == 0 && lane < 8) {
#pragma unroll
        for (int w = 0; w < 8; w++) h += sred[w][lane];
    }
    return h;   // valid in warp0 lanes 0-7
}

// ============ stage 1: y1 = A1@x1, y2 = A2@x2 (dual mv1) ==================
// epilogue: store y; stats over relu(y*w_j + b_j), j=0..3 (slot = mat, M=4N)
__global__ void __launch_bounds__(256) k_s1(
    const float* __restrict__ A1, const float* __restrict__ A2,
    const float* __restrict__ x,
    const float* __restrict__ w11, const float* __restrict__ b11,
    const float* __restrict__ w21, const float* __restrict__ b21, int bpm) {
    int mat = blockIdx.x >= bpm;
    const float4* __restrict__ A4 = (const float4*)(mat ? A2 : A1);
    const float4* __restrict__ z4 = (const float4*)(x + (mat ? NR : 0));
    const float* w = mat ? w21 : w11;
    const float* b = mat ? b21 : b11;
    float* yout = mat ? g_y2 : g_y1;
    int row0 = (blockIdx.x - mat * bpm) * 8;
    int tid = threadIdx.x;

    float acc[8];
#pragma unroll
    for (int r = 0; r < 8; r++) acc[r] = 0.f;
#pragma unroll 2
    for (int it = 0; it < 8; it++) {
        int cg = it * 256 + tid;
        float4 zv = __ldg(&z4[cg]);
#pragma unroll
        for (int r = 0; r < 8; r++) {
            float4 av = __ldcs(&A4[(size_t)(row0 + r) * 2048 + cg]);
            acc[r] += av.x * zv.x + av.y * zv.y + av.z * zv.z + av.w * zv.w;
        }
    }
    __shared__ float sred[8][8];
    float y = red8(acc, sred);
    if ((tid >> 5) == 0) {
        int lane = tid & 31;
        float s = 0.f, q = 0.f;
        if (lane < 8) {
            yout[row0 + lane] = y;
#pragma unroll
            for (int j = 0; j < 4; j++) {
                float h = fmaxf(fmaf(y, w[j], b[j]), 0.f);
                s += h; q += h * h;
            }
        }
        stat_add(mat, blockIdx.x & (SB - 1), s, q);
    }
}

// ===== glue1: BN slots0/1 (M=4N); z = (sc*relu(y*w+b)+sh) @ w_2 ===========
__global__ void k_glue1(const float* __restrict__ w11, const float* __restrict__ b11,
                        const float* __restrict__ w21, const float* __restrict__ b21,
                        const float* __restrict__ w12, const float* __restrict__ w22,
                        const float* __restrict__ gamma, const float* __restrict__ beta) {
    int tid = threadIdx.x;
    __shared__ float sbn[4];
    if (tid < 32)      bn_warp(0, 4.f * NR, *gamma, *beta, sbn);
    else if (tid < 64) bn_warp(1, 4.f * NR, *gamma, *beta, sbn + 2);
    __syncthreads();
    if (blockIdx.x == 0 && tid < 128) g_stats[640 + tid] = 0.0;  // zero slot 5
    int i = blockIdx.x * 256 + tid;
    float y1 = g_y1[i], y2 = g_y2[i];
    float z1 = 0.f, z2 = 0.f;
#pragma unroll
    for (int j = 0; j < 4; j++) {
        float h1 = fmaxf(fmaf(y1, w11[j], b11[j]), 0.f);
        float h2 = fmaxf(fmaf(y2, w21[j], b21[j]), 0.f);
        z1 += (sbn[0] * h1 + sbn[1]) * w12[j];
        z2 += (sbn[2] * h2 + sbn[3]) * w22[j];
    }
    g_z1[i] = z1;
    g_z2[i] = z2;
}

// ============ stage 2: r = relu(A@z + b) (dual mv1), stats slot2/3 ========
__global__ void __launch_bounds__(256) k_s2(
    const float* __restrict__ A1, const float* __restrict__ A2,
    const float* __restrict__ b12, const float* __restrict__ b22, int bpm) {
    int mat = blockIdx.x >= bpm;
    const float4* __restrict__ A4 = (const float4*)(mat ? A2 : A1);
    const float4* __restrict__ z4 = (const float4*)(mat ? g_z2 : g_z1);
    const float* b = mat ? b22 : b12;
    float* rout = mat ? g_r2 : g_r1;
    int row0 = (blockIdx.x - mat * bpm) * 8;
    int tid = threadIdx.x;

    float acc[8];
#pragma unroll
    for (int r = 0; r < 8; r++) acc[r] = 0.f;
#pragma unroll 2
    for (int it = 0; it < 8; it++) {
        int cg = it * 256 + tid;
        float4 zv = __ldg(&z4[cg]);
#pragma unroll
        for (int r = 0; r < 8; r++) {
            float4 av = __ldcs(&A4[(size_t)(row0 + r) * 2048 + cg]);
            acc[r] += av.x * zv.x + av.y * zv.y + av.z * zv.z + av.w * zv.w;
        }
    }
    __shared__ float sred[8][8];
    float y = red8(acc, sred);
    if ((tid >> 5) == 0) {
        int lane = tid & 31;
        float rv = 0.f;
        if (lane < 8) {
            rv = fmaxf(y + b[0], 0.f);
            rout[row0 + lane] = rv;
        }
        stat_add(2 + mat, blockIdx.x & (SB - 1), rv, rv * rv);
    }
}

// ===== glue2: BN slots2/3 (M=N) + post-relu -> F columns ==================
__global__ void k_glue2(const float* __restrict__ gamma,
                        const float* __restrict__ beta) {
    int tid = threadIdx.x;
    __shared__ float sbn[4];
    if (tid < 32)      bn_warp(2, (float)NR, *gamma, *beta, sbn);
    else if (tid < 64) bn_warp(3, (float)NR, *gamma, *beta, sbn + 2);
    __syncthreads();
    if (blockIdx.x == 0 && tid < 256) g_stats[tid] = 0.0;  // zero slots 0,1
    int i = blockIdx.x * 256 + tid;
    g_fa[i] = fmaxf(sbn[0] * g_r1[i] + sbn[1], 0.f);
    g_fb[i] = fmaxf(sbn[2] * g_r2[i] + sbn[3], 0.f);
}

// ============ stage C1: G = A12 @ [fa, fb]  (mv2), stats slot4 ============
__global__ void __launch_bounds__(256) k_s3(
    const float* __restrict__ A12,
    const float* __restrict__ wc1, const float* __restrict__ bc1) {
    const float4* __restrict__ A4  = (const float4*)A12;
    const float4* __restrict__ fa4 = (const float4*)g_fa;
    const float4* __restrict__ fb4 = (const float4*)g_fb;
    int row0 = blockIdx.x * 8;
    int tid = threadIdx.x;

    float acc0[8], acc1[8];
#pragma unroll
    for (int r = 0; r < 8; r++) { acc0[r] = 0.f; acc1[r] = 0.f; }
#pragma unroll 2
    for (int it = 0; it < 8; it++) {
        int cg = it * 256 + tid;
        float4 fa = __ldg(&fa4[cg]);
        float4 fb = __ldg(&fb4[cg]);
#pragma unroll
        for (int r = 0; r < 8; r++) {
            float4 av = __ldcs(&A4[(size_t)(row0 + r) * 2048 + cg]);
            acc0[r] += av.x * fa.x + av.y * fa.y + av.z * fa.z + av.w * fa.w;
            acc1[r] += av.x * fb.x + av.y * fb.y + av.z * fb.z + av.w * fb.w;
        }
    }
    __shared__ float sred[2][8][8];
    int lane = tid & 31, warp = tid >> 5;
#pragma unroll
    for (int v = 0; v < 8; v++) {
        float v0 = acc0[v], v1 = acc1[v];
#pragma unroll
        for (int off = 16; off; off >>= 1) {
            v0 += __shfl_xor_sync(0xffffffffu, v0, off);
            v1 += __shfl_xor_sync(0xffffffffu, v1, off);
        }
        if (lane == v) { sred[0][warp][v] = v0; sred[1][warp][v] = v1; }
    }
    __syncthreads();
    if (warp == 0) {
        float s = 0.f, q = 0.f;
        if (lane < 8) {
            float G0 = 0.f, G1 = 0.f;
#pragma unroll
            for (int w = 0; w < 8; w++) { G0 += sred[0][w][lane]; G1 += sred[1][w][lane]; }
            g_Ga[row0 + lane] = G0;
            g_Gb[row0 + lane] = G1;
#pragma unroll
            for (int j = 0; j < 4; j++) {
                float h = fmaxf(G0 * wc1[j] + G1 * wc1[4 + j] + bc1[j], 0.f);
                s += h; q += h * h;
            }
        }
        stat_add(4, blockIdx.x & (SB - 1), s, q);
    }
}

// ===== glue3: BN slot4 (M=4N); z = (sc*relu(h)+sh) @ wc2 ==================
__global__ void k_glue3(const float* __restrict__ wc1, const float* __restrict__ bc1,
                        const float* __restrict__ wc2,
                        const float* __restrict__ gamma, const float* __restrict__ beta) {
    int tid = threadIdx.x;
    __shared__ float sbn[2];
    if (tid < 32) bn_warp(4, 4.f * NR, *gamma, *beta, sbn);
    __syncthreads();
    if (blockIdx.x == 0 && tid < 256) g_stats[256 + tid] = 0.0;  // zero slots 2,3
    int i = blockIdx.x * 256 + tid;
    float G0 = g_Ga[i], G1 = g_Gb[i];
    float z = 0.f;
#pragma unroll
    for (int j = 0; j < 4; j++) {
        float h = fmaxf(G0 * wc1[j] + G1 * wc1[4 + j] + bc1[j], 0.f);
        z += (sbn[0] * h + sbn[1]) * wc2[j];
    }
    g_z1[i] = z;
}

// ============ stage C2: r = relu(A12@z + bc2) (mv1), stats slot5 ==========
__global__ void __launch_bounds__(256) k_s4(
    const float* __restrict__ A12, const float* __restrict__ bc2) {
    const float4* __restrict__ A4 = (const float4*)A12;
    const float4* __restrict__ z4 = (const float4*)g_z1;
    int row0 = blockIdx.x * 8;
    int tid = threadIdx.x;

    float acc[8];
#pragma unroll
    for (int r = 0; r < 8; r++) acc[r] = 0.f;
#pragma unroll 2
    for (int it = 0; it < 8; it++) {
        int cg = it * 256 + tid;
        float4 zv = __ldg(&z4[cg]);
#pragma unroll
        for (int r = 0; r < 8; r++) {
            float4 av = __ldcs(&A4[(size_t)(row0 + r) * 2048 + cg]);
            acc[r] += av.x * zv.x + av.y * zv.y + av.z * zv.z + av.w * zv.w;
        }
    }
    __shared__ float sred[8][8];
    float y = red8(acc, sred);
    if ((tid >> 5) == 0) {
        int lane = tid & 31;
        float rv = 0.f;
        if (lane < 8) {
            rv = fmaxf(y + bc2[0], 0.f);
            g_r1[row0 + lane] = rv;
        }
        stat_add(5, blockIdx.x & (SB - 1), rv, rv * rv);
    }
}

// ===== out: BN slot5 (M=N) + relu ==========================================
__global__ void k_out(const float* __restrict__ gamma,
                      const float* __restrict__ beta,
                      float* __restrict__ out) {
    int tid = threadIdx.x;
    __shared__ float sbn[2];
    if (tid < 32) bn_warp(5, (float)NR, *gamma, *beta, sbn);
    __syncthreads();
    if (blockIdx.x == 0 && tid < 128) g_stats[512 + tid] = 0.0;  // zero slot 4
    int i = blockIdx.x * 256 + tid;
    out[i] = fmaxf(sbn[0] * g_r1[i] + sbn[1], 0.f);
}

// ---------------- host ----------------------------------------------------
extern "C" void kernel_launch(void* const* d_in, const int* in_sizes, int n_in,
                              void* d_out, int out_size) {
    const float* x     = (const float*)d_in[0];
    const float* adj   = (const float*)d_in[1];
    const float* w11   = (const float*)d_in[2];
    const float* b11   = (const float*)d_in[3];
    const float* w12   = (const float*)d_in[4];
    const float* b12   = (const float*)d_in[5];
    const float* w21   = (const float*)d_in[6];
    const float* b21   = (const float*)d_in[7];
    const float* w22   = (const float*)d_in[8];
    const float* b22   = (const float*)d_in[9];
    const float* wc1   = (const float*)d_in[10];
    const float* bc1   = (const float*)d_in[11];
    const float* wc2   = (const float*)d_in[12];
    const float* bc2   = (const float*)d_in[13];
    const float* gamma = (const float*)d_in[14];
    const float* beta  = (const float*)d_in[15];

    const float* A1  = adj;
    const float* A2  = adj + NN;
    const float* A12 = adj + 2 * NN;
    float* out = (float*)d_out;

    const int bpm = NR / 8;  // 1024 row-tiles per matrix

    k_s1<<<2 * bpm, 256>>>(A1, A2, x, w11, b11, w21, b21, bpm);
    k_glue1<<<NR / 256, 256>>>(w11, b11, w21, b21, w12, w22, gamma, beta);
    k_s2<<<2 * bpm, 256>>>(A1, A2, b12, b22, bpm);
    k_glue2<<<NR / 256, 256>>>(gamma, beta);
    k_s3<<<bpm, 256>>>(A12, wc1, bc1);
    k_glue3<<<NR / 256, 256>>>(wc1, bc1, wc2, gamma, beta);
    k_s4<<<bpm, 256>>>(A12, bc2);
    k_out<<<NR / 256, 256>>>(gamma, beta, out);
}